// round 1
// baseline (speedup 1.0000x reference)
#include <cuda_runtime.h>
#include <cstdint>

// Problem constants
#define T_STEPS 512
#define HDIM    128
#define G4      512     // 4*H
#define OUTD    64
#define BSEL    255     // only batch row that affects the output

// ---------------- scratch (no allocations allowed) ----------------
__device__ float g_xg[T_STEPS * G4];     // precomputed input gates for batch 255
__device__ float g_hout[256 * HDIM];     // h[255, 256+j, :]
__device__ float g_Wc[OUTD * HDIM];      // W2 @ W1
__device__ float g_bc[OUTD];             // W2 @ b1 + b2

// ---------------- helpers ----------------
__device__ __forceinline__ float fast_sigmoid(float x) {
    return 1.0f / (1.0f + __expf(-x));
}
__device__ __forceinline__ float fast_tanh(float x) {
    // tanh(x) = 1 - 2/(exp(2x)+1); saturates correctly for large |x|
    return 1.0f - 2.0f / (__expf(2.0f * x) + 1.0f);
}
__device__ __forceinline__ void fma_f32x2(unsigned long long& acc,
                                          unsigned long long a,
                                          unsigned long long b) {
    asm("fma.rn.f32x2 %0, %1, %2, %0;" : "+l"(acc) : "l"(a), "l"(b));
}
#define CLUSTER_SYNC() do { \
    asm volatile("barrier.cluster.arrive.aligned;" ::: "memory"); \
    asm volatile("barrier.cluster.wait.aligned;"   ::: "memory"); \
} while (0)

// ---------------- kernel 1: xg[t, j] = W_ih[j,:] . x[255,t,:] + b_ih[j] + b_hh[j]
// grid 64 blocks, each handles 8 timesteps; 512 threads = one gate row each.
__global__ void __launch_bounds__(512) xg_kernel(
    const float* __restrict__ x, const float* __restrict__ Wih,
    const float* __restrict__ bih, const float* __restrict__ bhh)
{
    __shared__ __align__(16) float xs[8][HDIM];
    int t0 = blockIdx.x * 8;
    int j  = threadIdx.x;

    for (int i = j; i < 8 * HDIM; i += 512) {
        int tt = i >> 7, d = i & 127;
        xs[tt][d] = x[((size_t)BSEL * T_STEPS + t0 + tt) * HDIM + d];
    }
    __syncthreads();

    const float4* wr4 = reinterpret_cast<const float4*>(Wih + j * HDIM);
    float acc[8];
    #pragma unroll
    for (int tt = 0; tt < 8; tt++) acc[tt] = 0.0f;

    #pragma unroll
    for (int q = 0; q < HDIM / 4; q++) {
        float4 w = wr4[q];
        #pragma unroll
        for (int tt = 0; tt < 8; tt++) {
            float4 xv = reinterpret_cast<const float4*>(xs[tt])[q];
            acc[tt] += w.x * xv.x + w.y * xv.y + w.z * xv.z + w.w * xv.w;
        }
    }
    float bb = bih[j] + bhh[j];
    #pragma unroll
    for (int tt = 0; tt < 8; tt++)
        g_xg[(t0 + tt) * G4 + j] = acc[tt] + bb;
}

// ---------------- kernel 2: collapse the two affine layers
// Wc = W2 @ W1  (64x128), bc = W2 @ b1 + b2
__global__ void __launch_bounds__(512) mlp_precomp_kernel(
    const float* __restrict__ W1, const float* __restrict__ b1,
    const float* __restrict__ W2, const float* __restrict__ b2)
{
    int idx = blockIdx.x * blockDim.x + threadIdx.x;
    if (idx < OUTD * HDIM) {
        int o = idx >> 7, hh = idx & 127;
        float acc = 0.0f;
        #pragma unroll 4
        for (int m = 0; m < HDIM; m++)
            acc += W2[o * HDIM + m] * W1[m * HDIM + hh];
        g_Wc[idx] = acc;
    }
    if (idx < OUTD) {
        float acc = b2[idx];
        #pragma unroll 4
        for (int m = 0; m < HDIM; m++)
            acc += W2[idx * HDIM + m] * b1[m];
        g_bc[idx] = acc;
    }
}

// ---------------- kernel 3: the sequential LSTM scan (batch 255 only)
// 2-CTA cluster, 512 threads each. W_hh fully register-resident:
//   thread = (row_local, half); row_local in [0,256) -> gate = row_local>>6,
//   eLocal = row_local&63, element e = rank*64 + eLocal, global row = gate*128 + e.
//   Each thread holds 64 weights (32 f32x2 pairs) of its row-half.
__global__ void __cluster_dims__(2, 1, 1) __launch_bounds__(512, 1)
lstm_scan_kernel(const float* __restrict__ Whh)
{
    __shared__ __align__(16) float h_buf[HDIM];
    __shared__ float c_buf[64];
    __shared__ float gpre[256];

    int tid = threadIdx.x;
    unsigned rank;
    asm("mov.u32 %0, %%cluster_ctarank;" : "=r"(rank));

    int row_local = tid >> 1;
    int half      = tid & 1;
    int gate      = row_local >> 6;
    int eLocal    = row_local & 63;
    int e         = (int)rank * 64 + eLocal;
    int grow      = gate * HDIM + e;

    // register-resident weights: 32 packed f32x2 = 64 floats
    unsigned long long w2[32];
    {
        const unsigned long long* wsrc =
            reinterpret_cast<const unsigned long long*>(Whh + grow * HDIM + half * 64);
        #pragma unroll
        for (int q = 0; q < 32; q++) w2[q] = wsrc[q];
    }

    if (tid < HDIM) h_buf[tid] = 0.0f;
    if (tid < 64)   c_buf[tid] = 0.0f;
    __syncthreads();
    CLUSTER_SYNC();

    const unsigned long long* hp =
        reinterpret_cast<const unsigned long long*>(h_buf) + half * 32;
    const float* xg_row = g_xg + grow;

    for (int t = 0; t < T_STEPS; t++) {
        // prefetch xg early: does not depend on h, overlaps matvec latency
        float xgv = 0.0f;
        if (half == 0) xgv = __ldg(xg_row + t * G4);

        // matvec half-dot: 32 packed FMAs, 4 accumulators
        unsigned long long a0 = 0ull, a1 = 0ull, a2 = 0ull, a3 = 0ull;
        #pragma unroll
        for (int q = 0; q < 32; q += 4) {
            fma_f32x2(a0, w2[q + 0], hp[q + 0]);
            fma_f32x2(a1, w2[q + 1], hp[q + 1]);
            fma_f32x2(a2, w2[q + 2], hp[q + 2]);
            fma_f32x2(a3, w2[q + 3], hp[q + 3]);
        }
        float x0, y0, x1, y1, x2, y2, x3, y3;
        asm("mov.b64 {%0,%1}, %2;" : "=f"(x0), "=f"(y0) : "l"(a0));
        asm("mov.b64 {%0,%1}, %2;" : "=f"(x1), "=f"(y1) : "l"(a1));
        asm("mov.b64 {%0,%1}, %2;" : "=f"(x2), "=f"(y2) : "l"(a2));
        asm("mov.b64 {%0,%1}, %2;" : "=f"(x3), "=f"(y3) : "l"(a3));
        float acc = ((x0 + x1) + (x2 + x3)) + ((y0 + y1) + (y2 + y3));

        // combine the two halves of the row via in-warp shuffle (lanes 2r, 2r+1)
        float acco = __shfl_xor_sync(0xFFFFFFFFu, acc, 1);
        if (half == 0) gpre[row_local] = acc + acco + xgv;
        __syncthreads();

        // gate math: thread tid<64 owns element (rank*64 + tid)
        if (tid < 64) {
            float gi = gpre[tid];
            float gf = gpre[64 + tid];
            float gg = gpre[128 + tid];
            float go = gpre[192 + tid];
            float iv = fast_sigmoid(gi);
            float fv = fast_sigmoid(gf);
            float gv = fast_tanh(gg);
            float ov = fast_sigmoid(go);
            float c  = fv * c_buf[tid] + iv * gv;
            c_buf[tid] = c;
            float h  = ov * fast_tanh(c);

            int ee = (int)rank * 64 + tid;
            h_buf[ee] = h;
            // mirror into peer CTA's h_buf via DSMEM
            uint32_t laddr, paddr;
            asm("{ .reg .u64 t; cvta.to.shared.u64 t, %1; cvt.u32.u64 %0, t; }"
                : "=r"(laddr) : "l"(&h_buf[ee]));
            asm("mapa.shared::cluster.u32 %0, %1, %2;"
                : "=r"(paddr) : "r"(laddr), "r"(rank ^ 1u));
            asm volatile("st.shared::cluster.f32 [%0], %1;"
                         :: "r"(paddr), "f"(h) : "memory");

            if (t >= 256) g_hout[(t - 256) * HDIM + ee] = h;
        }
        // release local+DSMEM writes, acquire peer's writes
        CLUSTER_SYNC();
    }
}

// ---------------- kernel 4: out[j, o] = bc[o] + Wc[o,:] . h[255, 256+j, :]
__global__ void __launch_bounds__(64) mlp_final_kernel(float* __restrict__ out)
{
    __shared__ __align__(16) float hs[HDIM];
    int j = blockIdx.x;
    int o = threadIdx.x;
    hs[o]      = g_hout[j * HDIM + o];
    hs[o + 64] = g_hout[j * HDIM + 64 + o];
    __syncthreads();

    const float4* wr4 = reinterpret_cast<const float4*>(g_Wc + o * HDIM);
    float a0 = 0.0f, a1 = 0.0f;
    #pragma unroll
    for (int q = 0; q < HDIM / 4; q += 2) {
        float4 w0 = wr4[q],     x0 = reinterpret_cast<const float4*>(hs)[q];
        float4 w1 = wr4[q + 1], x1 = reinterpret_cast<const float4*>(hs)[q + 1];
        a0 += w0.x * x0.x + w0.y * x0.y + w0.z * x0.z + w0.w * x0.w;
        a1 += w1.x * x1.x + w1.y * x1.y + w1.z * x1.z + w1.w * x1.w;
    }
    out[j * OUTD + o] = g_bc[o] + a0 + a1;
}

// ---------------- launch ----------------
extern "C" void kernel_launch(void* const* d_in, const int* in_sizes, int n_in,
                              void* d_out, int out_size)
{
    const float* x   = (const float*)d_in[0];
    const float* Wih = (const float*)d_in[1];
    const float* Whh = (const float*)d_in[2];
    const float* bih = (const float*)d_in[3];
    const float* bhh = (const float*)d_in[4];
    const float* W1  = (const float*)d_in[5];
    const float* b1  = (const float*)d_in[6];
    const float* W2  = (const float*)d_in[7];
    const float* b2  = (const float*)d_in[8];
    float* out = (float*)d_out;

    xg_kernel<<<64, 512>>>(x, Wih, bih, bhh);
    mlp_precomp_kernel<<<16, 512>>>(W1, b1, W2, b2);
    lstm_scan_kernel<<<2, 512>>>(Whh);
    mlp_final_kernel<<<256, 64>>>(out);
}